// round 8
// baseline (speedup 1.0000x reference)
#include <cuda_runtime.h>

// SWAP gate, DIM=2, C=0, T=1, WIRES=12 -> D=4096, BATCH=1024.
// out[k, :] = x[swap_bits_10_11(k), :] for both planes (involution).
// Row bits 10/11 == flat float4-index bits 18/19 (256 float4 per row).
//
// Persistent single-wave kernel: grid = 148 SMs x 8 blocks = 1184 blocks
// of 256 threads (one full residency wave), grid-stride loop (~3.5 iters)
// instead of 3.5 launch waves -> no wave-transition ramps; successive
// iterations' loads overlap prior stores.

#define D_DIM   4096
#define BATCH   1024
#define VEC_PER_ROW (BATCH / 4)          // 256 float4 per row
#define TOTAL_VEC (D_DIM * VEC_PER_ROW)  // 1,048,576 float4 per plane

#define NBLK 1184                        // 148 SMs * 8 CTAs
#define TPB  256

__global__ void __launch_bounds__(TPB) swap_gather_kernel(
    const float4* __restrict__ xr,
    const float4* __restrict__ xi,
    float4* __restrict__ out)   // [2, D, BATCH] as float4
{
    const unsigned stride = NBLK * TPB;  // 303,104

    for (unsigned idx = blockIdx.x * TPB + threadIdx.x;
         idx < TOTAL_VEC; idx += stride) {
        // swap bits 18 and 19 of the flat float4 index (== row bits 10/11)
        unsigned diff = ((idx >> 18) ^ (idx >> 19)) & 1u;
        unsigned src  = idx ^ (diff * 0xC0000u);

        float4 r = xr[src];
        float4 i = xi[src];
        out[idx] = r;
        out[TOTAL_VEC + idx] = i;
    }
}

extern "C" void kernel_launch(void* const* d_in, const int* in_sizes, int n_in,
                              void* d_out, int out_size) {
    const float4* xr = (const float4*)d_in[0];
    const float4* xi = (const float4*)d_in[1];
    // d_in[2] = U (permutation matrix) — closed form, unused.
    float4* out = (float4*)d_out;

    swap_gather_kernel<<<NBLK, TPB>>>(xr, xi, out);
}

// round 13
// speedup vs baseline: 1.0269x; 1.0269x over previous
#include <cuda_runtime.h>

// SWAP gate on qudits C=0, T=1, DIM=2, WIRES=12 -> D=4096, BATCH=1024.
// The permutation matrix U swaps digits C and T of the row index, i.e.
// out[k, b] = x[swap_bits_10_11(k), b] (involution) — the dense matmul
// collapses to a row-gather copy. U input is ignored.
//
// FINAL: this problem is LTS-throughput-bound. Total traffic = 67 MB
// (read 33.5 + write 33.5), all of it through the L2 slices regardless of
// hit/miss (LTS cap ~6300 B/cyc, path-independent). Floor = ~9.7 us; this
// kernel measures 10.7 us = ~91% of the cap. Five alternative shapes
// (MLP=8, .cs streaming stores, L2::evict_last v8.b32, persistent
// single-wave grid) all landed within 10.7-11.0 us, confirming the wall.

#define D_DIM   4096
#define BATCH   1024
#define VEC_PER_ROW (BATCH / 4)          // 256 float4 per row
#define TOTAL_VEC (D_DIM * VEC_PER_ROW)  // 1,048,576 float4 per plane

__global__ void __launch_bounds__(256) swap_gather_kernel(
    const float4* __restrict__ xr,
    const float4* __restrict__ xi,
    float4* __restrict__ out)   // [2, D, BATCH] as float4
{
    unsigned idx = blockIdx.x * blockDim.x + threadIdx.x;  // 0 .. TOTAL_VEC-1

    // swap bits 18 and 19 of the flat float4 index (== row bits 10/11)
    unsigned b18 = (idx >> 18) & 1u;
    unsigned b19 = (idx >> 19) & 1u;
    unsigned src = idx ^ ((b18 ^ b19) ? 0xC0000u : 0u);

    float4 r = xr[src];
    float4 i = xi[src];
    out[idx] = r;
    out[TOTAL_VEC + idx] = i;
}

extern "C" void kernel_launch(void* const* d_in, const int* in_sizes, int n_in,
                              void* d_out, int out_size) {
    const float4* xr = (const float4*)d_in[0];
    const float4* xi = (const float4*)d_in[1];
    // d_in[2] = U (permutation matrix) — closed form, unused.
    float4* out = (float4*)d_out;

    dim3 grid(TOTAL_VEC / 256);   // 4096 blocks
    dim3 block(256);
    swap_gather_kernel<<<grid, block>>>(xr, xi, out);
}